// round 1
// baseline (speedup 1.0000x reference)
#include <cuda_runtime.h>

// Problem constants (fixed by the dataset shapes)
#define KCODES 1024
#define DDIM   64
#define HW     4096            // h*w
#define NPTS   65536           // B*h*w
#define NELEM  4194304         // B*d*h*w

#define TILE_N 128
#define KC     64              // codes per chunk
#define NCHUNK (KCODES / KC)   // 16
#define CS_STRIDE 68           // padded (multiple of 4 floats -> 16B aligned rows)

// Output layout (floats), concatenated in reference return order
#define OFF_EK   0
#define OFF_IDX  4194304
#define OFF_L    4259840
#define OFF_CB   4259841
#define OFF_CNT  4325377
#define OFF_SUM  4326401

#define DECAY 0.99f
#define OMD   0.01f
#define EPSV  1e-5f

// Scratch (device globals: no allocation allowed)
__device__ float g_codebookT[DDIM * KCODES];
__device__ float g_cnorm[KCODES];
__device__ float g_counts[KCODES];
__device__ float g_sums[KCODES * DDIM];
__device__ float g_loss;

typedef unsigned long long u64;

__device__ __forceinline__ u64 ffma2(u64 a, u64 b, u64 c) {
    u64 d;
    asm("fma.rn.f32x2 %0, %1, %2, %3;" : "=l"(d) : "l"(a), "l"(b), "l"(c));
    return d;
}
__device__ __forceinline__ u64 pack2(float x, float y) {
    u64 r;
    asm("mov.b64 %0, {%1, %2};" : "=l"(r) : "f"(x), "f"(y));
    return r;
}
__device__ __forceinline__ float2 unpack2(u64 v) {
    float2 f;
    asm("mov.b64 {%0, %1}, %2;" : "=f"(f.x), "=f"(f.y) : "l"(v));
    return f;
}

// ---------------------------------------------------------------------------
// Kernel A: zero scratch, build transposed codebook [d][K] and code norms
// ---------------------------------------------------------------------------
__global__ void prep_kernel(const float* __restrict__ cb) {
    int t = blockIdx.x * blockDim.x + threadIdx.x;
    if (t < KCODES * DDIM) {
        float v = cb[t];
        int k = t >> 6;       // row (code)
        int c = t & 63;       // dim
        g_codebookT[c * KCODES + k] = v;
        g_sums[t] = 0.0f;
    }
    if (t < KCODES) {
        g_counts[t] = 0.0f;
        const float* row = cb + t * DDIM;
        float s = 0.0f;
#pragma unroll
        for (int c = 0; c < DDIM; c++) { float v = row[c]; s += v * v; }
        g_cnorm[t] = s;
    }
    if (t == 0) g_loss = 0.0f;
}

// ---------------------------------------------------------------------------
// Kernel B: fused distance-GEMM + argmin + gather/e_k + loss + EMA stats
// 512 CTAs x 256 threads; per CTA: 128 points vs all 1024 codes
// thread layout: tx = tid & 7 (8 code-groups), ty = tid >> 3 (32 point-groups)
// micro-tile: 4 points x 8 codes, accumulated as f32x2 pairs (fma.rn.f32x2)
// ---------------------------------------------------------------------------
__global__ __launch_bounds__(256, 4)
void vq_main(const float* __restrict__ z, const float* __restrict__ cb,
             float* __restrict__ out) {
    extern __shared__ float sm[];
    float* zs   = sm;                          // [DDIM][TILE_N]     32768 B
    float* cs   = sm + DDIM * TILE_N;          // [DDIM][CS_STRIDE]  17408 B
    float* cn   = cs + DDIM * CS_STRIDE;       // [KC]                 256 B
    int*   idxs = (int*)(cn + KC);             // [TILE_N]             512 B
    // post-mainloop aliases into cs region:
    float* redD = cs;                          // [128][8] floats
    int*   redI = (int*)(cs + TILE_N * 8);     // [128][8] ints
    int*   hist = (int*)cs + 2048;             // [KCODES] ints (4 KB)

    const int tid = threadIdx.x;
    const int tx = tid & 7;
    const int ty = tid >> 3;

    const int base = blockIdx.x * TILE_N;
    const int b    = base >> 12;               // batch
    const int rem  = base & 4095;              // y*64 (+x base)
    const float* zbase = z + (size_t)b * (DDIM * HW) + rem;

    // load z tile: zs[c][p] (coalesced, float4)
    for (int i = tid; i < (DDIM * TILE_N) / 4; i += 256) {
        int lin = i * 4;
        int c = lin >> 7;
        int p = lin & 127;
        *(float4*)(zs + c * TILE_N + p) = *(const float4*)(zbase + c * HW + p);
    }

    float best[4] = {1e30f, 1e30f, 1e30f, 1e30f};
    int   bidx[4] = {0, 0, 0, 0};

    for (int kc = 0; kc < NCHUNK; kc++) {
        __syncthreads();   // previous compute done (and first iter: zs stores done)
        // load code chunk (transposed layout) + norms
        for (int i = tid; i < (KC * DDIM) / 4; i += 256) {
            int lin = i * 4;
            int c  = lin >> 6;
            int kk = lin & 63;
            *(float4*)(cs + c * CS_STRIDE + kk) =
                *(const float4*)(g_codebookT + c * KCODES + kc * KC + kk);
        }
        if (tid < KC / 4)
            *(float4*)(cn + tid * 4) = *(const float4*)(g_cnorm + kc * KC + tid * 4);
        __syncthreads();

        u64 acc[4][4];
#pragma unroll
        for (int i = 0; i < 4; i++)
#pragma unroll
            for (int j = 0; j < 4; j++) acc[i][j] = 0ULL;

#pragma unroll 8
        for (int dd = 0; dd < DDIM; dd++) {
            float4 zq = *(const float4*)(zs + dd * TILE_N + ty * 4);
            ulonglong2 ca = *(const ulonglong2*)(cs + dd * CS_STRIDE + tx * 8);
            ulonglong2 cb2 = *(const ulonglong2*)(cs + dd * CS_STRIDE + tx * 8 + 4);
            u64 cp0 = ca.x, cp1 = ca.y, cp2 = cb2.x, cp3 = cb2.y;
            float zv[4] = {zq.x, zq.y, zq.z, zq.w};
#pragma unroll
            for (int i = 0; i < 4; i++) {
                u64 zz = pack2(zv[i], zv[i]);
                acc[i][0] = ffma2(zz, cp0, acc[i][0]);
                acc[i][1] = ffma2(zz, cp1, acc[i][1]);
                acc[i][2] = ffma2(zz, cp2, acc[i][2]);
                acc[i][3] = ffma2(zz, cp3, acc[i][3]);
            }
        }

        // fold chunk into running argmin (ascending k; strict < keeps earliest)
#pragma unroll
        for (int i = 0; i < 4; i++) {
#pragma unroll
            for (int j = 0; j < 4; j++) {
                float2 a = unpack2(acc[i][j]);
                int kl = tx * 8 + 2 * j;
                float d0 = cn[kl]     - 2.0f * a.x;
                float d1 = cn[kl + 1] - 2.0f * a.y;
                int kg = kc * KC + kl;
                if (d0 < best[i]) { best[i] = d0; bidx[i] = kg; }
                if (d1 < best[i]) { best[i] = d1; bidx[i] = kg + 1; }
            }
        }
    }

    __syncthreads();   // cs reads done everywhere -> safe to alias

    // cross-tx reduction per point
#pragma unroll
    for (int i = 0; i < 4; i++) {
        int p = ty * 4 + i;
        redD[p * 8 + tx] = best[i];
        redI[p * 8 + tx] = bidx[i];
    }
    // init histogram (disjoint smem region)
    for (int i = tid; i < KCODES; i += 256) hist[i] = 0;
    __syncthreads();

    if (tid < TILE_N) {
        int p = tid;
        float bd = redD[p * 8];
        int bi = redI[p * 8];
#pragma unroll
        for (int t = 1; t < 8; t++) {
            float d = redD[p * 8 + t];
            int ii = redI[p * 8 + t];
            if (d < bd || (d == bd && ii < bi)) { bd = d; bi = ii; }
        }
        idxs[p] = bi;
        out[OFF_IDX + base + p] = (float)bi;
        atomicAdd(&hist[bi], 1);
    }
    __syncthreads();

    // counts -> global (only touched bins)
    for (int i = tid; i < KCODES; i += 256) {
        int v = hist[i];
        if (v) atomicAdd(&g_counts[i], (float)v);
    }

    // gather e_k, commit-loss partial, scatter sums
    float* ekbase = out + OFF_EK + (size_t)b * (DDIM * HW) + rem;
    float sse = 0.0f;
    for (int i = tid; i < DDIM * TILE_N; i += 256) {
        int c = i >> 7;
        int p = i & 127;
        int kk = idxs[p];
        float cv = cb[kk * DDIM + c];
        float zv = zs[c * TILE_N + p];
        ekbase[c * HW + p] = cv;                      // coalesced in p
        float dlt = zv - cv;
        sse += dlt * dlt;
        atomicAdd(&g_sums[kk * DDIM + c], zv);
    }
    // warp-reduce loss, one atomic per warp
#pragma unroll
    for (int off = 16; off; off >>= 1)
        sse += __shfl_down_sync(0xffffffffu, sse, off);
    if ((tid & 31) == 0) atomicAdd(&g_loss, sse);
}

// ---------------------------------------------------------------------------
// Kernel C: EMA finalize + loss write (1 CTA, 1024 threads)
// ---------------------------------------------------------------------------
__global__ void finalize_kernel(const float* __restrict__ ema_count,
                                const float* __restrict__ ema_sum,
                                float* __restrict__ out) {
    __shared__ float warp_s[32];
    __shared__ float n_s;
    __shared__ float cs_s[KCODES];
    int t = threadIdx.x;

    float nc = ema_count[t] * DECAY + OMD * g_counts[t];
    out[OFF_CNT + t] = nc;

    float v = nc;
#pragma unroll
    for (int off = 16; off; off >>= 1)
        v += __shfl_down_sync(0xffffffffu, v, off);
    if ((t & 31) == 0) warp_s[t >> 5] = v;
    __syncthreads();
    if (t == 0) {
        float n = 0.0f;
#pragma unroll
        for (int w = 0; w < 32; w++) n += warp_s[w];
        n_s = n;
        out[OFF_L] = 1.25f * g_loss * (1.0f / (float)NELEM);
    }
    __syncthreads();
    float n = n_s;
    cs_s[t] = (nc + EPSV) / (n + (float)KCODES * EPSV) * n;
    __syncthreads();

    for (int i = t; i < KCODES * DDIM; i += 1024) {
        int k = i >> 6;
        float ns = ema_sum[i] * DECAY + OMD * g_sums[i];
        out[OFF_SUM + i] = ns;
        out[OFF_CB + i]  = ns / cs_s[k];
    }
}

// ---------------------------------------------------------------------------
extern "C" void kernel_launch(void* const* d_in, const int* in_sizes, int n_in,
                              void* d_out, int out_size) {
    (void)in_sizes; (void)n_in; (void)out_size;
    const float* z         = (const float*)d_in[0];
    const float* cb        = (const float*)d_in[1];
    const float* ema_count = (const float*)d_in[2];
    const float* ema_sum   = (const float*)d_in[3];
    float* out = (float*)d_out;

    const int smem_bytes =
        (DDIM * TILE_N + DDIM * CS_STRIDE + KC) * 4 + TILE_N * 4;  // 50944

    prep_kernel<<<(KCODES * DDIM + 255) / 256, 256>>>(cb);
    cudaFuncSetAttribute(vq_main, cudaFuncAttributeMaxDynamicSharedMemorySize,
                         smem_bytes);
    vq_main<<<NPTS / TILE_N, 256, smem_bytes>>>(z, cb, out);
    finalize_kernel<<<1, 1024>>>(ema_count, ema_sum, out);
}

// round 2
// speedup vs baseline: 1.0279x; 1.0279x over previous
#include <cuda_runtime.h>

// Problem constants (fixed by the dataset shapes)
#define KCODES 1024
#define DDIM   64
#define HW     4096            // h*w
#define NPTS   65536           // B*h*w
#define NELEM  4194304         // B*d*h*w

#define TILE_N 128
#define KC     64              // codes per chunk
#define NCHUNK (KCODES / KC)   // 16
#define CS_STRIDE 68           // padded (multiple of 4 floats -> 16B aligned rows)

// Output layout (floats), concatenated in reference return order
#define OFF_EK   0
#define OFF_IDX  4194304
#define OFF_L    4259840
#define OFF_CB   4259841
#define OFF_CNT  4325377
#define OFF_SUM  4326401

#define DECAY 0.99f
#define OMD   0.01f
#define EPSV  1e-5f

// Scratch (device globals: no allocation allowed)
__device__ float g_codebookT[DDIM * KCODES];
__device__ float g_cnorm[KCODES];
__device__ float g_counts[KCODES];
__device__ float g_sums[KCODES * DDIM];
__device__ float g_loss;

typedef unsigned long long u64;

__device__ __forceinline__ u64 ffma2(u64 a, u64 b, u64 c) {
    u64 d;
    asm("fma.rn.f32x2 %0, %1, %2, %3;" : "=l"(d) : "l"(a), "l"(b), "l"(c));
    return d;
}
__device__ __forceinline__ u64 pack2(float x, float y) {
    u64 r;
    asm("mov.b64 %0, {%1, %2};" : "=l"(r) : "f"(x), "f"(y));
    return r;
}
__device__ __forceinline__ float2 unpack2(u64 v) {
    float2 f;
    asm("mov.b64 {%0, %1}, %2;" : "=f"(f.x), "=f"(f.y) : "l"(v));
    return f;
}

// ---------------------------------------------------------------------------
// Kernel A: zero scratch, build transposed codebook [d][K] and code norms.
// 256 blocks x 256 threads; block b covers codes 4b..4b+3 (256 elements).
// Norms via warp-shuffle reduce (each warp = half of one code row).
// ---------------------------------------------------------------------------
__global__ void prep_kernel(const float* __restrict__ cb) {
    __shared__ float s8[8];
    int t = blockIdx.x * blockDim.x + threadIdx.x;   // 0..65535
    float v = cb[t];                                  // coalesced
    int k = t >> 6;       // code row
    int c = t & 63;       // dim
    g_codebookT[c * KCODES + k] = v;
    g_sums[t] = 0.0f;

    float sq = v * v;
#pragma unroll
    for (int off = 16; off; off >>= 1)
        sq += __shfl_down_sync(0xffffffffu, sq, off);
    if ((threadIdx.x & 31) == 0) s8[threadIdx.x >> 5] = sq;
    __syncthreads();
    if (threadIdx.x < 4) {
        int kk = (blockIdx.x << 2) + threadIdx.x;
        g_counts[kk] = 0.0f;
        g_cnorm[kk] = s8[2 * threadIdx.x] + s8[2 * threadIdx.x + 1];
    }
    if (t == 0) g_loss = 0.0f;
}

// ---------------------------------------------------------------------------
// Kernel B: fused distance-GEMM + argmin + gather/e_k + loss + EMA stats
// 512 CTAs x 256 threads; per CTA: 128 points vs all 1024 codes
// thread layout: tx = tid & 7 (8 code-groups), ty = tid >> 3 (32 point-groups)
// micro-tile: 4 points x 8 codes, accumulated as f32x2 pairs (fma.rn.f32x2)
// __launch_bounds__(256, 2): 128 regs/thread -> no accumulator spills.
// ---------------------------------------------------------------------------
__global__ __launch_bounds__(256, 2)
void vq_main(const float* __restrict__ z, const float* __restrict__ cb,
             float* __restrict__ out) {
    extern __shared__ float sm[];
    float* zs   = sm;                          // [DDIM][TILE_N]     32768 B
    float* cs   = sm + DDIM * TILE_N;          // [DDIM][CS_STRIDE]  17408 B
    float* cn   = cs + DDIM * CS_STRIDE;       // [KC]                 256 B
    int*   idxs = (int*)(cn + KC);             // [TILE_N]             512 B
    // post-mainloop aliases into cs region:
    float* redD = cs;                          // [128][8] floats
    int*   redI = (int*)(cs + TILE_N * 8);     // [128][8] ints
    int*   hist = (int*)cs + 2048;             // [KCODES] ints (4 KB)

    const int tid = threadIdx.x;
    const int tx = tid & 7;
    const int ty = tid >> 3;

    const int base = blockIdx.x * TILE_N;
    const int b    = base >> 12;               // batch
    const int rem  = base & 4095;              // y*64 (+x base)
    const float* zbase = z + (size_t)b * (DDIM * HW) + rem;

    // load z tile: zs[c][p] (coalesced, float4)
    for (int i = tid; i < (DDIM * TILE_N) / 4; i += 256) {
        int lin = i * 4;
        int c = lin >> 7;
        int p = lin & 127;
        *(float4*)(zs + c * TILE_N + p) = *(const float4*)(zbase + c * HW + p);
    }

    float best[4] = {1e30f, 1e30f, 1e30f, 1e30f};
    int   bidx[4] = {0, 0, 0, 0};

    for (int kc = 0; kc < NCHUNK; kc++) {
        __syncthreads();   // previous compute done (and first iter: zs stores done)
        // load code chunk (transposed layout) + norms
        for (int i = tid; i < (KC * DDIM) / 4; i += 256) {
            int lin = i * 4;
            int c  = lin >> 6;
            int kk = lin & 63;
            *(float4*)(cs + c * CS_STRIDE + kk) =
                *(const float4*)(g_codebookT + c * KCODES + kc * KC + kk);
        }
        if (tid < KC / 4)
            *(float4*)(cn + tid * 4) = *(const float4*)(g_cnorm + kc * KC + tid * 4);
        __syncthreads();

        u64 acc[4][4];
#pragma unroll
        for (int i = 0; i < 4; i++)
#pragma unroll
            for (int j = 0; j < 4; j++) acc[i][j] = 0ULL;

#pragma unroll 8
        for (int dd = 0; dd < DDIM; dd++) {
            float4 zq = *(const float4*)(zs + dd * TILE_N + ty * 4);
            ulonglong2 ca = *(const ulonglong2*)(cs + dd * CS_STRIDE + tx * 8);
            ulonglong2 cb2 = *(const ulonglong2*)(cs + dd * CS_STRIDE + tx * 8 + 4);
            u64 cp0 = ca.x, cp1 = ca.y, cp2 = cb2.x, cp3 = cb2.y;
            float zv[4] = {zq.x, zq.y, zq.z, zq.w};
#pragma unroll
            for (int i = 0; i < 4; i++) {
                u64 zz = pack2(zv[i], zv[i]);
                acc[i][0] = ffma2(zz, cp0, acc[i][0]);
                acc[i][1] = ffma2(zz, cp1, acc[i][1]);
                acc[i][2] = ffma2(zz, cp2, acc[i][2]);
                acc[i][3] = ffma2(zz, cp3, acc[i][3]);
            }
        }

        // fold chunk into running argmin (ascending k; strict < keeps earliest)
#pragma unroll
        for (int i = 0; i < 4; i++) {
#pragma unroll
            for (int j = 0; j < 4; j++) {
                float2 a = unpack2(acc[i][j]);
                int kl = tx * 8 + 2 * j;
                float d0 = cn[kl]     - 2.0f * a.x;
                float d1 = cn[kl + 1] - 2.0f * a.y;
                int kg = kc * KC + kl;
                if (d0 < best[i]) { best[i] = d0; bidx[i] = kg; }
                if (d1 < best[i]) { best[i] = d1; bidx[i] = kg + 1; }
            }
        }
    }

    __syncthreads();   // cs reads done everywhere -> safe to alias

    // cross-tx reduction per point
#pragma unroll
    for (int i = 0; i < 4; i++) {
        int p = ty * 4 + i;
        redD[p * 8 + tx] = best[i];
        redI[p * 8 + tx] = bidx[i];
    }
    // init histogram (disjoint smem region)
    for (int i = tid; i < KCODES; i += 256) hist[i] = 0;
    __syncthreads();

    if (tid < TILE_N) {
        int p = tid;
        float bd = redD[p * 8];
        int bi = redI[p * 8];
#pragma unroll
        for (int t = 1; t < 8; t++) {
            float d = redD[p * 8 + t];
            int ii = redI[p * 8 + t];
            if (d < bd || (d == bd && ii < bi)) { bd = d; bi = ii; }
        }
        idxs[p] = bi;
        out[OFF_IDX + base + p] = (float)bi;
        atomicAdd(&hist[bi], 1);
    }
    __syncthreads();

    // counts -> global (only touched bins)
    for (int i = tid; i < KCODES; i += 256) {
        int v = hist[i];
        if (v) atomicAdd(&g_counts[i], (float)v);
    }

    // gather e_k, commit-loss partial, scatter sums
    float* ekbase = out + OFF_EK + (size_t)b * (DDIM * HW) + rem;
    float sse = 0.0f;
    for (int i = tid; i < DDIM * TILE_N; i += 256) {
        int c = i >> 7;
        int p = i & 127;
        int kk = idxs[p];
        float cv = cb[kk * DDIM + c];
        float zv = zs[c * TILE_N + p];
        ekbase[c * HW + p] = cv;                      // coalesced in p
        float dlt = zv - cv;
        sse += dlt * dlt;
        atomicAdd(&g_sums[kk * DDIM + c], zv);
    }
    // warp-reduce loss, one atomic per warp
#pragma unroll
    for (int off = 16; off; off >>= 1)
        sse += __shfl_down_sync(0xffffffffu, sse, off);
    if ((tid & 31) == 0) atomicAdd(&g_loss, sse);
}

// ---------------------------------------------------------------------------
// Kernel C: EMA finalize + loss write (1 CTA, 1024 threads)
// ---------------------------------------------------------------------------
__global__ void finalize_kernel(const float* __restrict__ ema_count,
                                const float* __restrict__ ema_sum,
                                float* __restrict__ out) {
    __shared__ float warp_s[32];
    __shared__ float n_s;
    __shared__ float cs_s[KCODES];
    int t = threadIdx.x;

    float nc = ema_count[t] * DECAY + OMD * g_counts[t];
    out[OFF_CNT + t] = nc;

    float v = nc;
#pragma unroll
    for (int off = 16; off; off >>= 1)
        v += __shfl_down_sync(0xffffffffu, v, off);
    if ((t & 31) == 0) warp_s[t >> 5] = v;
    __syncthreads();
    if (t == 0) {
        float n = 0.0f;
#pragma unroll
        for (int w = 0; w < 32; w++) n += warp_s[w];
        n_s = n;
        out[OFF_L] = 1.25f * g_loss * (1.0f / (float)NELEM);
    }
    __syncthreads();
    float n = n_s;
    cs_s[t] = (nc + EPSV) / (n + (float)KCODES * EPSV) * n;
    __syncthreads();

    for (int i = t; i < KCODES * DDIM; i += 1024) {
        int k = i >> 6;
        float ns = ema_sum[i] * DECAY + OMD * g_sums[i];
        out[OFF_SUM + i] = ns;
        out[OFF_CB + i]  = ns / cs_s[k];
    }
}

// ---------------------------------------------------------------------------
extern "C" void kernel_launch(void* const* d_in, const int* in_sizes, int n_in,
                              void* d_out, int out_size) {
    (void)in_sizes; (void)n_in; (void)out_size;
    const float* z         = (const float*)d_in[0];
    const float* cb        = (const float*)d_in[1];
    const float* ema_count = (const float*)d_in[2];
    const float* ema_sum   = (const float*)d_in[3];
    float* out = (float*)d_out;

    const int smem_bytes =
        (DDIM * TILE_N + DDIM * CS_STRIDE + KC) * 4 + TILE_N * 4;  // 50944

    prep_kernel<<<256, 256>>>(cb);
    cudaFuncSetAttribute(vq_main, cudaFuncAttributeMaxDynamicSharedMemorySize,
                         smem_bytes);
    vq_main<<<NPTS / TILE_N, 256, smem_bytes>>>(z, cb, out);
    finalize_kernel<<<1, 1024>>>(ema_count, ema_sum, out);
}

// round 4
// speedup vs baseline: 1.7681x; 1.7201x over previous
#include <cuda_runtime.h>
#include <cstdint>

// Problem constants (fixed by dataset shapes)
#define KCODES 1024
#define DDIM   64
#define HW     4096
#define NPTS   65536
#define NELEM  4194304

#define TILE_N  128            // points per CTA
#define CHUNK_K 64             // codes per B chunk
#define NCHUNK  16

// Output layout (floats), concatenated in reference return order
#define OFF_EK   0
#define OFF_IDX  4194304
#define OFF_L    4259840
#define OFF_CB   4259841
#define OFF_CNT  4325377
#define OFF_SUM  4326401

#define DECAY 0.99f
#define OMD   0.01f
#define EPSV  1e-5f

// SMEM byte offsets (dynamic smem)
#define SM_ZS    0          // [64][128] f32 z staging        32768 B
#define SM_CN    32768      // 1024 f32 code norms             4096 B
#define SM_IDX   36864      // 128 int indices                  512 B
#define SM_B     37376      // 2 bufs x (hi 17408 + lo 17408) 69632 B
#define SM_BYTES 107008
#define B_BUF_BYTES 34816   // one buffer (hi part + lo part)
#define B_PART_WORDS 4352   // 64 codes * 68 words

// Scratch globals (no allocation allowed). tf32-truncated hi + residual lo.
__device__ __align__(16) float g_cbhi[KCODES * DDIM];
__device__ __align__(16) float g_cblo[KCODES * DDIM];
__device__ float g_cnorm[KCODES];
__device__ float g_counts[KCODES];
__device__ float g_sums[KCODES * DDIM];
__device__ float g_loss;

// ---------------------------------------------------------------------------
__device__ __forceinline__ uint32_t smem_u32(const void* p) {
    uint32_t a;
    asm("{ .reg .u64 t; cvta.to.shared.u64 t, %1; cvt.u32.u64 %0, t; }"
        : "=r"(a) : "l"(p));
    return a;
}
__device__ __forceinline__ uint32_t f2tf32(float f) {
    uint32_t r;
    asm("cvt.rna.tf32.f32 %0, %1;" : "=r"(r) : "f"(f));
    return r;
}
__device__ __forceinline__ void mma_tf32(float& c0, float& c1, float& c2, float& c3,
                                         uint32_t a0, uint32_t a1, uint32_t a2,
                                         uint32_t a3, uint32_t b0, uint32_t b1) {
    asm volatile(
        "mma.sync.aligned.m16n8k8.row.col.f32.tf32.tf32.f32 "
        "{%0,%1,%2,%3}, {%4,%5,%6,%7}, {%8,%9}, {%0,%1,%2,%3};"
        : "+f"(c0), "+f"(c1), "+f"(c2), "+f"(c3)
        : "r"(a0), "r"(a1), "r"(a2), "r"(a3), "r"(b0), "r"(b1));
}
__device__ __forceinline__ void cp_async16(uint32_t dst, const void* src) {
    asm volatile("cp.async.ca.shared.global [%0], [%1], 16;"
                 :: "r"(dst), "l"(src));
}
__device__ __forceinline__ void cp_commit() {
    asm volatile("cp.async.commit_group;");
}
__device__ __forceinline__ void cp_wait_all() {
    asm volatile("cp.async.wait_group 0;");
}

// ---------------------------------------------------------------------------
// Kernel A: split codebook into tf32 hi/lo, exact f32 norms, zero scratch.
// 256 blocks x 256 threads; block covers 4 code rows.
// ---------------------------------------------------------------------------
__global__ void prep_kernel(const float* __restrict__ cb) {
    __shared__ float s8[8];
    int t = blockIdx.x * blockDim.x + threadIdx.x;   // 0..65535
    float v = cb[t];
    uint32_t hb = f2tf32(v);
    float hf = __uint_as_float(hb);
    g_cbhi[t] = hf;
    g_cblo[t] = __uint_as_float(f2tf32(v - hf));
    g_sums[t] = 0.0f;

    float sq = v * v;
#pragma unroll
    for (int off = 16; off; off >>= 1)
        sq += __shfl_down_sync(0xffffffffu, sq, off);
    if ((threadIdx.x & 31) == 0) s8[threadIdx.x >> 5] = sq;
    __syncthreads();
    if (threadIdx.x < 4) {
        int kk = (blockIdx.x << 2) + threadIdx.x;
        g_counts[kk] = 0.0f;
        g_cnorm[kk] = s8[2 * threadIdx.x] + s8[2 * threadIdx.x + 1];
    }
    if (t == 0) g_loss = 0.0f;
}

// ---------------------------------------------------------------------------
// Kernel B: tf32-split mma.sync distance GEMM + argmin + epilogue
// 512 CTAs x 256 threads; CTA = 128 points x 1024 codes.
// Warp w owns points [16w, 16w+16); A (z hi/lo) lives in registers.
// B chunks of 64 codes double-buffered in smem via cp.async.
// ---------------------------------------------------------------------------
__global__ __launch_bounds__(256, 2)
void vq_main(const float* __restrict__ z, const float* __restrict__ cb,
             float* __restrict__ out) {
    extern __shared__ float sm[];
    char* smb = (char*)sm;
    float* zs   = sm;                       // [64][128] f32
    float* cn_s = (float*)(smb + SM_CN);
    int*   idxs = (int*)(smb + SM_IDX);
    const uint32_t sbase = smem_u32(sm);

    const int tid  = threadIdx.x;
    const int w    = tid >> 5;
    const int lane = tid & 31;
    const int g    = lane >> 2;             // 0..7  (point row / B col)
    const int q    = lane & 3;              // 0..3  (k sub / D col pair)
    const int pb   = w * 16;

    const int base = blockIdx.x * TILE_N;
    const int b    = base >> 12;
    const int rem  = base & 4095;
    const float* zbase = z + (size_t)b * (DDIM * HW) + rem;

    // load z tile [c][p] coalesced + code norms
    for (int i = tid; i < (DDIM * TILE_N) / 4; i += 256) {
        int lin = i * 4;
        int c = lin >> 7;
        int p = lin & 127;
        *(float4*)(zs + c * TILE_N + p) = *(const float4*)(zbase + c * HW + p);
    }
    for (int i = tid; i < KCODES; i += 256) cn_s[i] = g_cnorm[i];

    // prefetch first B chunk (codes 0..63, hi+lo) while we build A fragments
    auto prefetch = [&](int buf, int k0) {
#pragma unroll
        for (int it = 0; it < 8; it++) {
            int u    = tid + it * 256;          // 0..2047
            int part = u >> 10;
            int u2   = u & 1023;
            int code = u2 >> 4;
            int d4   = (u2 & 15) * 4;
            const float* src = (part ? g_cblo : g_cbhi) + (k0 + code) * DDIM + d4;
            uint32_t dst = sbase + SM_B + buf * B_BUF_BYTES + part * 17408
                         + (code * 68 + d4) * 4;
            cp_async16(dst, src);
        }
        cp_commit();
    };
    prefetch(0, 0);
    __syncthreads();   // zs ready

    // Build A fragments in registers: 8 k-steps x 4 regs x {hi,lo}
    uint32_t ahi[8][4], alo[8][4];
#pragma unroll
    for (int kk = 0; kk < 8; kk++) {
        int c0 = kk * 8 + q, c1 = c0 + 4;
        float v00 = zs[c0 * TILE_N + pb + g];
        float v10 = zs[c0 * TILE_N + pb + g + 8];
        float v01 = zs[c1 * TILE_N + pb + g];
        float v11 = zs[c1 * TILE_N + pb + g + 8];
        ahi[kk][0] = f2tf32(v00);
        ahi[kk][1] = f2tf32(v10);
        ahi[kk][2] = f2tf32(v01);
        ahi[kk][3] = f2tf32(v11);
        alo[kk][0] = f2tf32(v00 - __uint_as_float(ahi[kk][0]));
        alo[kk][1] = f2tf32(v10 - __uint_as_float(ahi[kk][1]));
        alo[kk][2] = f2tf32(v01 - __uint_as_float(ahi[kk][2]));
        alo[kk][3] = f2tf32(v11 - __uint_as_float(ahi[kk][3]));
    }

    float bd0 = 1e30f, bd1 = 1e30f;
    int   bi0 = 0,     bi1 = 0;

    for (int c = 0; c < NCHUNK; c++) {
        const int buf = c & 1;
        cp_wait_all();
        __syncthreads();                     // chunk c in smem; prev compute done
        if (c < NCHUNK - 1) prefetch(buf ^ 1, (c + 1) * CHUNK_K);

        const uint32_t* Bh = (const uint32_t*)(smb + SM_B + buf * B_BUF_BYTES);
        const uint32_t* Bl = Bh + B_PART_WORDS;

#pragma unroll 1
        for (int t = 0; t < 8; t++) {        // 8 n8-tiles per chunk
            float a0 = 0.f, a1 = 0.f, a2 = 0.f, a3 = 0.f;
            const int woB = (t * 8 + g) * 68 + q;
#pragma unroll
            for (int kk = 0; kk < 8; kk++) {
                uint32_t bh0 = Bh[woB + kk * 8];
                uint32_t bh1 = Bh[woB + kk * 8 + 4];
                uint32_t bl0 = Bl[woB + kk * 8];
                uint32_t bl1 = Bl[woB + kk * 8 + 4];
                mma_tf32(a0, a1, a2, a3, ahi[kk][0], ahi[kk][1], ahi[kk][2],
                         ahi[kk][3], bh0, bh1);
                mma_tf32(a0, a1, a2, a3, ahi[kk][0], ahi[kk][1], ahi[kk][2],
                         ahi[kk][3], bl0, bl1);
                mma_tf32(a0, a1, a2, a3, alo[kk][0], alo[kk][1], alo[kk][2],
                         alo[kk][3], bh0, bh1);
            }
            // acc layout: a0=(row g, col 2q) a1=(g, 2q+1) a2=(g+8, 2q) a3=(g+8, 2q+1)
            const int ck = c * CHUNK_K + t * 8;
            float n0 = cn_s[ck + 2 * q];
            float n1 = cn_s[ck + 2 * q + 1];
            float d;
            d = n0 - 2.0f * a0; if (d < bd0) { bd0 = d; bi0 = ck + 2 * q; }
            d = n1 - 2.0f * a1; if (d < bd0) { bd0 = d; bi0 = ck + 2 * q + 1; }
            d = n0 - 2.0f * a2; if (d < bd1) { bd1 = d; bi1 = ck + 2 * q; }
            d = n1 - 2.0f * a3; if (d < bd1) { bd1 = d; bi1 = ck + 2 * q + 1; }
        }
    }

    // reduce argmin across the 4 q-lanes of each point row
#pragma unroll
    for (int off = 1; off <= 2; off <<= 1) {
        float od = __shfl_xor_sync(0xffffffffu, bd0, off);
        int   oi = __shfl_xor_sync(0xffffffffu, bi0, off);
        if (od < bd0 || (od == bd0 && oi < bi0)) { bd0 = od; bi0 = oi; }
        od = __shfl_xor_sync(0xffffffffu, bd1, off);
        oi = __shfl_xor_sync(0xffffffffu, bi1, off);
        if (od < bd1 || (od == bd1 && oi < bi1)) { bd1 = od; bi1 = oi; }
    }
    if (q == 0) {
        idxs[pb + g]     = bi0;
        idxs[pb + g + 8] = bi1;
        out[OFF_IDX + base + pb + g]     = (float)bi0;
        out[OFF_IDX + base + pb + g + 8] = (float)bi1;
    }
    __syncthreads();

    // ------------- epilogue: hist, e_k, loss, EMA stats -------------
    int* hist = (int*)(smb + SM_B);          // alias B region
    for (int i = tid; i < KCODES; i += 256) hist[i] = 0;
    __syncthreads();
    if (tid < TILE_N) atomicAdd(&hist[idxs[tid]], 1);
    __syncthreads();

    for (int i = tid; i < KCODES; i += 256) {
        int v = hist[i];
        if (v) atomicAdd(&g_counts[i], (float)v);
    }

    float* ekbase = out + OFF_EK + (size_t)b * (DDIM * HW) + rem;
    float sse = 0.0f;
    for (int i = tid; i < DDIM * TILE_N; i += 256) {
        int cc = i >> 7;
        int p  = i & 127;
        int kk = idxs[p];
        float cv = cb[kk * DDIM + cc];
        float zv = zs[cc * TILE_N + p];
        ekbase[cc * HW + p] = cv;            // coalesced in p
        float dlt = zv - cv;
        sse += dlt * dlt;
        atomicAdd(&g_sums[kk * DDIM + cc], zv);
    }
#pragma unroll
    for (int off = 16; off; off >>= 1)
        sse += __shfl_down_sync(0xffffffffu, sse, off);
    if ((tid & 31) == 0) atomicAdd(&g_loss, sse);
}

// ---------------------------------------------------------------------------
// Kernel C: EMA finalize + loss write (1 CTA, 1024 threads)
// ---------------------------------------------------------------------------
__global__ void finalize_kernel(const float* __restrict__ ema_count,
                                const float* __restrict__ ema_sum,
                                float* __restrict__ out) {
    __shared__ float warp_s[32];
    __shared__ float n_s;
    __shared__ float cs_s[KCODES];
    int t = threadIdx.x;

    float nc = ema_count[t] * DECAY + OMD * g_counts[t];
    out[OFF_CNT + t] = nc;

    float v = nc;
#pragma unroll
    for (int off = 16; off; off >>= 1)
        v += __shfl_down_sync(0xffffffffu, v, off);
    if ((t & 31) == 0) warp_s[t >> 5] = v;
    __syncthreads();
    if (t == 0) {
        float n = 0.0f;
#pragma unroll
        for (int w = 0; w < 32; w++) n += warp_s[w];
        n_s = n;
        out[OFF_L] = 1.25f * g_loss * (1.0f / (float)NELEM);
    }
    __syncthreads();
    float n = n_s;
    cs_s[t] = (nc + EPSV) / (n + (float)KCODES * EPSV) * n;
    __syncthreads();

    for (int i = t; i < KCODES * DDIM; i += 1024) {
        int k = i >> 6;
        float ns = ema_sum[i] * DECAY + OMD * g_sums[i];
        out[OFF_SUM + i] = ns;
        out[OFF_CB + i]  = ns / cs_s[k];
    }
}

// ---------------------------------------------------------------------------
extern "C" void kernel_launch(void* const* d_in, const int* in_sizes, int n_in,
                              void* d_out, int out_size) {
    (void)in_sizes; (void)n_in; (void)out_size;
    const float* z         = (const float*)d_in[0];
    const float* cb        = (const float*)d_in[1];
    const float* ema_count = (const float*)d_in[2];
    const float* ema_sum   = (const float*)d_in[3];
    float* out = (float*)d_out;

    prep_kernel<<<256, 256>>>(cb);
    cudaFuncSetAttribute(vq_main, cudaFuncAttributeMaxDynamicSharedMemorySize,
                         SM_BYTES);
    vq_main<<<NPTS / TILE_N, 256, SM_BYTES>>>(z, cb, out);
    finalize_kernel<<<1, 1024>>>(ema_count, ema_sum, out);
}

// round 5
// speedup vs baseline: 2.4896x; 1.4081x over previous
#include <cuda_runtime.h>
#include <cuda_fp16.h>
#include <cstdint>

// Problem constants (fixed by dataset shapes)
#define KCODES 1024
#define DDIM   64
#define HW     4096
#define NPTS   65536
#define NELEM  4194304

#define TILE_N  128            // points per CTA
#define CHUNK_K 64             // codes per B chunk
#define NCHUNK  16

// Output layout (floats), concatenated in reference return order
#define OFF_EK   0
#define OFF_IDX  4194304
#define OFF_L    4259840
#define OFF_CB   4259841
#define OFF_CNT  4325377
#define OFF_SUM  4326401

#define DECAY 0.99f
#define OMD   0.01f
#define EPSV  1e-5f

// SMEM byte offsets (dynamic smem)
#define SM_ZS    0          // [64][128] f32 z staging        32768 B
#define SM_CN    32768      // 1024 f32 code norms             4096 B
#define SM_IDX   36864      // 128 int indices                  512 B
#define SM_B     37376      // 2 bufs x (hi 9216 + lo 9216)   36864 B
#define SM_BYTES 74240
#define B_BUF_BYTES 18432   // one buffer (hi part + lo part)
#define B_PART_WORDS 2304   // 9216 / 4
#define B_ROW_WORDS 36      // 32 data words (64 f16) + 4 pad -> conflict-free

// Scratch globals (no allocation allowed). fp16 hi + fp16 residual lo.
__device__ __align__(16) __half g_cbhi[KCODES * DDIM];
__device__ __align__(16) __half g_cblo[KCODES * DDIM];
__device__ float g_cnorm[KCODES];
__device__ float g_counts[KCODES];
__device__ float g_sums[KCODES * DDIM];
__device__ float g_loss;

// ---------------------------------------------------------------------------
__device__ __forceinline__ uint32_t smem_u32(const void* p) {
    uint32_t a;
    asm("{ .reg .u64 t; cvta.to.shared.u64 t, %1; cvt.u32.u64 %0, t; }"
        : "=r"(a) : "l"(p));
    return a;
}
__device__ __forceinline__ uint32_t pack_h2(float x, float y) {
    __half2 h = __floats2half2_rn(x, y);
    return *(uint32_t*)&h;
}
__device__ __forceinline__ void mma_f16(float& c0, float& c1, float& c2, float& c3,
                                        uint32_t a0, uint32_t a1, uint32_t a2,
                                        uint32_t a3, uint32_t b0, uint32_t b1) {
    asm volatile(
        "mma.sync.aligned.m16n8k16.row.col.f32.f16.f16.f32 "
        "{%0,%1,%2,%3}, {%4,%5,%6,%7}, {%8,%9}, {%0,%1,%2,%3};"
        : "+f"(c0), "+f"(c1), "+f"(c2), "+f"(c3)
        : "r"(a0), "r"(a1), "r"(a2), "r"(a3), "r"(b0), "r"(b1));
}
__device__ __forceinline__ void cp_async16(uint32_t dst, const void* src) {
    asm volatile("cp.async.ca.shared.global [%0], [%1], 16;"
                 :: "r"(dst), "l"(src));
}
__device__ __forceinline__ void cp_commit() {
    asm volatile("cp.async.commit_group;");
}
__device__ __forceinline__ void cp_wait_all() {
    asm volatile("cp.async.wait_group 0;");
}

// ---------------------------------------------------------------------------
// Kernel A: split codebook into fp16 hi/lo, exact f32 norms, zero scratch.
// ---------------------------------------------------------------------------
__global__ void prep_kernel(const float* __restrict__ cb) {
    __shared__ float s8[8];
    int t = blockIdx.x * blockDim.x + threadIdx.x;   // 0..65535
    float v = cb[t];
    __half hi = __float2half_rn(v);
    g_cbhi[t] = hi;
    g_cblo[t] = __float2half_rn(v - __half2float(hi));
    g_sums[t] = 0.0f;

    float sq = v * v;
#pragma unroll
    for (int off = 16; off; off >>= 1)
        sq += __shfl_down_sync(0xffffffffu, sq, off);
    if ((threadIdx.x & 31) == 0) s8[threadIdx.x >> 5] = sq;
    __syncthreads();
    if (threadIdx.x < 4) {
        int kk = (blockIdx.x << 2) + threadIdx.x;
        g_counts[kk] = 0.0f;
        g_cnorm[kk] = s8[2 * threadIdx.x] + s8[2 * threadIdx.x + 1];
    }
    if (t == 0) g_loss = 0.0f;
}

// ---------------------------------------------------------------------------
// Kernel B: fp16-split m16n8k16 distance GEMM + argmin + epilogue
// 512 CTAs x 256 threads; CTA = 128 points x 1024 codes.
// Warp w owns points [16w, 16w+16); A (z hi/lo) lives in registers.
// B chunks of 64 codes double-buffered in smem via cp.async.
// ---------------------------------------------------------------------------
__global__ __launch_bounds__(256, 2)
void vq_main(const float* __restrict__ z, const float* __restrict__ cb,
             float* __restrict__ out) {
    extern __shared__ float sm[];
    char* smb = (char*)sm;
    float* zs   = sm;                       // [64][128] f32
    float* cn_s = (float*)(smb + SM_CN);
    int*   idxs = (int*)(smb + SM_IDX);
    const uint32_t sbase = smem_u32(sm);

    const int tid  = threadIdx.x;
    const int w    = tid >> 5;
    const int lane = tid & 31;
    const int g    = lane >> 2;             // 0..7  (point row / B code col)
    const int q    = lane & 3;              // 0..3  (k pair / D col pair)
    const int pb   = w * 16;

    const int base = blockIdx.x * TILE_N;
    const int b    = base >> 12;
    const int rem  = base & 4095;
    const float* zbase = z + (size_t)b * (DDIM * HW) + rem;

    // load z tile [c][p] coalesced + code norms
    for (int i = tid; i < (DDIM * TILE_N) / 4; i += 256) {
        int lin = i * 4;
        int c = lin >> 7;
        int p = lin & 127;
        *(float4*)(zs + c * TILE_N + p) = *(const float4*)(zbase + c * HW + p);
    }
    for (int i = tid; i < KCODES; i += 256) cn_s[i] = g_cnorm[i];

    // prefetch B chunk: hi/lo fp16, per code row = 32 data words + 4 pad
    auto prefetch = [&](int buf, int k0) {
#pragma unroll
        for (int it = 0; it < 4; it++) {
            int u    = tid + it * 256;          // 0..1023
            int part = u >> 9;
            int u2   = u & 511;
            int code = u2 >> 3;                 // 0..63
            int g16  = u2 & 7;                  // 16B granule in row
            const __half* src =
                (part ? g_cblo : g_cbhi) + (k0 + code) * DDIM + g16 * 8;
            uint32_t dst = sbase + SM_B + buf * B_BUF_BYTES + part * 9216
                         + code * (B_ROW_WORDS * 4) + g16 * 16;
            cp_async16(dst, src);
        }
        cp_commit();
    };
    prefetch(0, 0);
    __syncthreads();   // zs ready

    // Build A fragments in registers: 4 k16-steps x 4 regs x {hi,lo}
    uint32_t ahi[4][4], alo[4][4];
    const int p0 = pb + g, p1 = pb + g + 8;
#pragma unroll
    for (int kk = 0; kk < 4; kk++) {
        int cA = kk * 16 + 2 * q;           // low k pair base
#pragma unroll
        for (int half = 0; half < 2; half++) {   // 0: k-low pair, 1: k-high (+8)
            int c0 = cA + half * 8;
            float x0 = zs[c0 * TILE_N + p0];
            float y0 = zs[(c0 + 1) * TILE_N + p0];
            float x1 = zs[c0 * TILE_N + p1];
            float y1 = zs[(c0 + 1) * TILE_N + p1];
            float hx0 = __half2float(__float2half_rn(x0));
            float hy0 = __half2float(__float2half_rn(y0));
            float hx1 = __half2float(__float2half_rn(x1));
            float hy1 = __half2float(__float2half_rn(y1));
            ahi[kk][half * 2]     = pack_h2(hx0, hy0);
            ahi[kk][half * 2 + 1] = pack_h2(hx1, hy1);
            alo[kk][half * 2]     = pack_h2(x0 - hx0, y0 - hy0);
            alo[kk][half * 2 + 1] = pack_h2(x1 - hx1, y1 - hy1);
        }
    }

    float bd0 = 1e30f, bd1 = 1e30f;
    int   bi0 = 0,     bi1 = 0;

    for (int c = 0; c < NCHUNK; c++) {
        const int buf = c & 1;
        cp_wait_all();
        __syncthreads();                     // chunk c in smem; prev compute done
        if (c < NCHUNK - 1) prefetch(buf ^ 1, (c + 1) * CHUNK_K);

        const uint32_t* Bh = (const uint32_t*)(smb + SM_B + buf * B_BUF_BYTES);
        const uint32_t* Bl = Bh + B_PART_WORDS;

#pragma unroll 1
        for (int t = 0; t < 8; t++) {        // 8 n8-tiles per chunk
            float a0 = 0.f, a1 = 0.f, a2 = 0.f, a3 = 0.f;
            const int wo = (t * 8 + g) * B_ROW_WORDS + q;
#pragma unroll
            for (int kk = 0; kk < 4; kk++) {
                uint32_t bh0 = Bh[wo + kk * 8];
                uint32_t bh1 = Bh[wo + kk * 8 + 4];
                uint32_t bl0 = Bl[wo + kk * 8];
                uint32_t bl1 = Bl[wo + kk * 8 + 4];
                mma_f16(a0, a1, a2, a3, ahi[kk][0], ahi[kk][1], ahi[kk][2],
                        ahi[kk][3], bh0, bh1);
                mma_f16(a0, a1, a2, a3, ahi[kk][0], ahi[kk][1], ahi[kk][2],
                        ahi[kk][3], bl0, bl1);
                mma_f16(a0, a1, a2, a3, alo[kk][0], alo[kk][1], alo[kk][2],
                        alo[kk][3], bh0, bh1);
            }
            // acc layout: a0=(g, 2q) a1=(g, 2q+1) a2=(g+8, 2q) a3=(g+8, 2q+1)
            const int ck = c * CHUNK_K + t * 8;
            float n0 = cn_s[ck + 2 * q];
            float n1 = cn_s[ck + 2 * q + 1];
            float d;
            d = n0 - 2.0f * a0; if (d < bd0) { bd0 = d; bi0 = ck + 2 * q; }
            d = n1 - 2.0f * a1; if (d < bd0) { bd0 = d; bi0 = ck + 2 * q + 1; }
            d = n0 - 2.0f * a2; if (d < bd1) { bd1 = d; bi1 = ck + 2 * q; }
            d = n1 - 2.0f * a3; if (d < bd1) { bd1 = d; bi1 = ck + 2 * q + 1; }
        }
    }

    // reduce argmin across the 4 q-lanes of each point row
#pragma unroll
    for (int off = 1; off <= 2; off <<= 1) {
        float od = __shfl_xor_sync(0xffffffffu, bd0, off);
        int   oi = __shfl_xor_sync(0xffffffffu, bi0, off);
        if (od < bd0 || (od == bd0 && oi < bi0)) { bd0 = od; bi0 = oi; }
        od = __shfl_xor_sync(0xffffffffu, bd1, off);
        oi = __shfl_xor_sync(0xffffffffu, bi1, off);
        if (od < bd1 || (od == bd1 && oi < bi1)) { bd1 = od; bi1 = oi; }
    }
    if (q == 0) {
        idxs[pb + g]     = bi0;
        idxs[pb + g + 8] = bi1;
        out[OFF_IDX + base + pb + g]     = (float)bi0;
        out[OFF_IDX + base + pb + g + 8] = (float)bi1;
    }
    __syncthreads();

    // ------------- epilogue: hist, e_k, loss, EMA stats -------------
    int* hist = (int*)(smb + SM_B);          // alias B region
    for (int i = tid; i < KCODES; i += 256) hist[i] = 0;
    __syncthreads();
    if (tid < TILE_N) atomicAdd(&hist[idxs[tid]], 1);
    __syncthreads();

    for (int i = tid; i < KCODES; i += 256) {
        int v = hist[i];
        if (v) atomicAdd(&g_counts[i], (float)v);
    }

    float* ekbase = out + OFF_EK + (size_t)b * (DDIM * HW) + rem;
    float sse = 0.0f;
    for (int i = tid; i < DDIM * TILE_N; i += 256) {
        int cc = i >> 7;
        int p  = i & 127;
        int kk = idxs[p];
        float cv = cb[kk * DDIM + cc];
        float zv = zs[cc * TILE_N + p];
        ekbase[cc * HW + p] = cv;            // coalesced in p
        float dlt = zv - cv;
        sse += dlt * dlt;
        atomicAdd(&g_sums[kk * DDIM + cc], zv);
    }
#pragma unroll
    for (int off = 16; off; off >>= 1)
        sse += __shfl_down_sync(0xffffffffu, sse, off);
    if ((tid & 31) == 0) atomicAdd(&g_loss, sse);
}

// ---------------------------------------------------------------------------
// Kernel C: EMA finalize + loss write (1 CTA, 1024 threads)
// ---------------------------------------------------------------------------
__global__ void finalize_kernel(const float* __restrict__ ema_count,
                                const float* __restrict__ ema_sum,
                                float* __restrict__ out) {
    __shared__ float warp_s[32];
    __shared__ float n_s;
    __shared__ float cs_s[KCODES];
    int t = threadIdx.x;

    float nc = ema_count[t] * DECAY + OMD * g_counts[t];
    out[OFF_CNT + t] = nc;

    float v = nc;
#pragma unroll
    for (int off = 16; off; off >>= 1)
        v += __shfl_down_sync(0xffffffffu, v, off);
    if ((t & 31) == 0) warp_s[t >> 5] = v;
    __syncthreads();
    if (t == 0) {
        float n = 0.0f;
#pragma unroll
        for (int w = 0; w < 32; w++) n += warp_s[w];
        n_s = n;
        out[OFF_L] = 1.25f * g_loss * (1.0f / (float)NELEM);
    }
    __syncthreads();
    float n = n_s;
    cs_s[t] = (nc + EPSV) / (n + (float)KCODES * EPSV) * n;
    __syncthreads();

    for (int i = t; i < KCODES * DDIM; i += 1024) {
        int k = i >> 6;
        float ns = ema_sum[i] * DECAY + OMD * g_sums[i];
        out[OFF_SUM + i] = ns;
        out[OFF_CB + i]  = ns / cs_s[k];
    }
}

// ---------------------------------------------------------------------------
extern "C" void kernel_launch(void* const* d_in, const int* in_sizes, int n_in,
                              void* d_out, int out_size) {
    (void)in_sizes; (void)n_in; (void)out_size;
    const float* z         = (const float*)d_in[0];
    const float* cb        = (const float*)d_in[1];
    const float* ema_count = (const float*)d_in[2];
    const float* ema_sum   = (const float*)d_in[3];
    float* out = (float*)d_out;

    prep_kernel<<<256, 256>>>(cb);
    cudaFuncSetAttribute(vq_main, cudaFuncAttributeMaxDynamicSharedMemorySize,
                         SM_BYTES);
    vq_main<<<NPTS / TILE_N, 256, SM_BYTES>>>(z, cb, out);
    finalize_kernel<<<1, 1024>>>(ema_count, ema_sum, out);
}